// round 17
// baseline (speedup 1.0000x reference)
#include <cuda_runtime.h>
#include <cuda_fp16.h>
#include <math.h>
#include <cstdint>

// Problem constants
#define Bsz 4
#define Ssz 2048
#define Dsz 1024
#define Hh  16
#define DKk 64
#define Mrows (Bsz * Ssz)   // 8192

// ---------------------------------------------------------------------------
// Scratch (device globals) — plain fp16 everywhere
// ---------------------------------------------------------------------------
__device__ unsigned short g_xh[(long long)Mrows * Dsz];
__device__ unsigned short g_ch[(long long)Mrows * Dsz];
__device__ unsigned short g_wh[4ll * Dsz * Dsz];
__device__ unsigned short g_Qh[(long long)Mrows * Dsz];
__device__ unsigned short g_Kh[(long long)Mrows * Dsz];
__device__ unsigned short g_Vh[(long long)Mrows * Dsz];

// ---------------------------------------------------------------------------
// PTX helpers (portable ISA: ldmatrix / mma.sync / cp.async, sm_80+)
// ---------------------------------------------------------------------------
__device__ __forceinline__ uint32_t smem_to_u32(const void* p) {
    uint32_t a;
    asm("{ .reg .u64 t; cvta.to.shared.u64 t, %1; cvt.u32.u64 %0, t; }"
        : "=r"(a) : "l"(p));
    return a;
}
__device__ __forceinline__ void ldsm4(uint32_t* r, uint32_t addr) {
    asm volatile("ldmatrix.sync.aligned.m8n8.x4.shared.b16 {%0,%1,%2,%3}, [%4];"
                 : "=r"(r[0]), "=r"(r[1]), "=r"(r[2]), "=r"(r[3]) : "r"(addr));
}
__device__ __forceinline__ void ldsm4t(uint32_t* r, uint32_t addr) {
    asm volatile("ldmatrix.sync.aligned.m8n8.x4.trans.shared.b16 {%0,%1,%2,%3}, [%4];"
                 : "=r"(r[0]), "=r"(r[1]), "=r"(r[2]), "=r"(r[3]) : "r"(addr));
}
__device__ __forceinline__ void mma16816h(float* d, const uint32_t* a,
                                          const uint32_t* b) {
    asm volatile(
        "mma.sync.aligned.m16n8k16.row.col.f32.f16.f16.f32 "
        "{%0,%1,%2,%3}, {%4,%5,%6,%7}, {%8,%9}, {%0,%1,%2,%3};"
        : "+f"(d[0]), "+f"(d[1]), "+f"(d[2]), "+f"(d[3])
        : "r"(a[0]), "r"(a[1]), "r"(a[2]), "r"(a[3]), "r"(b[0]), "r"(b[1]));
}
__device__ __forceinline__ void cp_async16(uint32_t saddr, const void* g) {
    asm volatile("cp.async.cg.shared.global [%0], [%1], 16;"
                 :: "r"(saddr), "l"(g));
}
#define CP_COMMIT() asm volatile("cp.async.commit_group;" ::: "memory")
#define CP_WAIT0()  asm volatile("cp.async.wait_group 0;" ::: "memory")

__device__ __forceinline__ uint32_t packh(float a, float b) {
    __half2 h = __floats2half2_rn(a, b);
    return *reinterpret_cast<uint32_t*>(&h);
}

// ---------------------------------------------------------------------------
// Conversion kernels
// ---------------------------------------------------------------------------
__global__ __launch_bounds__(256)
void convert_f16_kernel(const float4* __restrict__ src,
                        uint2* __restrict__ dst, int n4) {
    int i = blockIdx.x * blockDim.x + threadIdx.x;
    if (i >= n4) return;
    float4 v = src[i];
    dst[i] = make_uint2(packh(v.x, v.y), packh(v.z, v.w));
}
__global__ __launch_bounds__(256)
void convert_w_kernel(const float4* __restrict__ wq, const float4* __restrict__ wk,
                      const float4* __restrict__ wv, const float4* __restrict__ wo,
                      int n4) {
    int i = blockIdx.x * blockDim.x + threadIdx.x;
    if (i >= n4) return;
    const float4* srcs[4] = {wq, wk, wv, wo};
    float4 v = srcs[blockIdx.y][i];
    uint2* dst = (uint2*)(g_wh + (long long)blockIdx.y * Dsz * Dsz);
    dst[i] = make_uint2(packh(v.x, v.y), packh(v.z, v.w));
}

// ---------------------------------------------------------------------------
// Plain fp16 NT GEMM — Round 17: BK=64 (half the barrier rounds, 128-MMA
// uninterrupted runs). CTA 128x128, 8 warps 4m x 2n.
// ---------------------------------------------------------------------------
#define ROWB 144                 // 64 halves (128 B) + 16 pad
#define MATB (128 * ROWB)        // 18432 B
#define GEMM_SMEM (2 * 2 * MATB) // 73728 B
#define NCHUNK (Dsz / 64)        // 16

__device__ __forceinline__ void gemm_mma(const unsigned short* __restrict__ Ah,
                                         const unsigned short* __restrict__ Wh,
                                         float* __restrict__ C,
                                         const float* __restrict__ bias,
                                         unsigned short* __restrict__ Dhi) {
    extern __shared__ char smem[];
    const uint32_t sbase = smem_to_u32(smem);
    const int tid = threadIdx.x;
    const int wid = tid >> 5;
    const int lane = tid & 31;
    const int wm = wid & 3;
    const int wn = wid >> 2;
    const int bm = blockIdx.y * 128;
    const int bn = blockIdx.x * 128;

    // load geometry: 1024 16B segs per matrix per chunk; 4 per thread
    // seg s: row = s>>3 (it-th row = tid>>3 + it*32), kseg = s&7 (8 halves)
    const int lr = tid >> 3;          // base row
    const int lc = (tid & 7) * 8;     // k offset in halves

    const unsigned short* gp[2] = {Ah, Wh};
    long long rb[2][4];
#pragma unroll
    for (int it = 0; it < 4; it++) {
        rb[0][it] = (long long)(bm + lr + it * 32) * Dsz + lc;
        rb[1][it] = (long long)(bn + lr + it * 32) * Dsz + lc;
    }

    float acc[2][8][4] = {};

    auto load_chunk = [&](int c, int buf) {
        const int k0 = c * 64;
        const uint32_t b = sbase + buf * 2 * MATB;
#pragma unroll
        for (int m = 0; m < 2; m++)
#pragma unroll
            for (int it = 0; it < 4; it++)
                cp_async16(b + m * MATB + (lr + it * 32) * ROWB + (tid & 7) * 16,
                           gp[m] + rb[m][it] + k0);
        CP_COMMIT();
    };

    const int mtx = lane >> 3;
    const int r8 = lane & 7;
    const int a_rowoff = (mtx & 1) * 8 + r8;
    const int a_segoff = (mtx >> 1);
    const int b_rowoff = (mtx >> 1) * 8 + r8;
    const int b_segoff = (mtx & 1);

    auto compute = [&](int buf) {
        const uint32_t ahb = sbase + buf * 2 * MATB;
        const uint32_t bhb = ahb + MATB;
#pragma unroll
        for (int ks = 0; ks < 4; ks++) {     // 4 k16 steps per 64-chunk
            uint32_t ah[2][4];
#pragma unroll
            for (int mt = 0; mt < 2; mt++) {
                uint32_t ao = (uint32_t)(wm * 32 + mt * 16 + a_rowoff) * ROWB +
                              (uint32_t)(ks * 2 + a_segoff) * 16;
                ldsm4(ah[mt], ahb + ao);
            }
#pragma unroll
            for (int np = 0; np < 4; np++) {
                uint32_t bo = (uint32_t)(wn * 64 + np * 16 + b_rowoff) * ROWB +
                              (uint32_t)(ks * 2 + b_segoff) * 16;
                uint32_t bh[4];
                ldsm4(bh, bhb + bo);
#pragma unroll
                for (int half = 0; half < 2; half++) {
                    const int nt = np * 2 + half;
#pragma unroll
                    for (int mt = 0; mt < 2; mt++)
                        mma16816h(acc[mt][nt], ah[mt], &bh[half * 2]);
                }
            }
        }
    };

    load_chunk(0, 0);
    for (int c = 0; c < NCHUNK; c++) {
        CP_WAIT0();
        __syncthreads();
        if (c + 1 < NCHUNK) load_chunk(c + 1, (c + 1) & 1);
        compute(c & 1);
    }

    const int g = lane >> 2, t = lane & 3;
    if (Dhi) {
#pragma unroll
        for (int mt = 0; mt < 2; mt++) {
#pragma unroll
            for (int nt = 0; nt < 8; nt++) {
                const int col = bn + wn * 64 + nt * 8 + t * 2;
                const int hd = col >> 6, d = col & 63;
#pragma unroll
                for (int hh = 0; hh < 2; hh++) {
                    const int row = bm + wm * 32 + mt * 16 + hh * 8 + g;
                    const int b = row >> 11, s = row & 2047;
                    const long long idx =
                        ((long long)(b * Hh + hd) * Ssz + s) * DKk + d;
                    *(uint32_t*)(Dhi + idx) =
                        packh(acc[mt][nt][hh * 2 + 0], acc[mt][nt][hh * 2 + 1]);
                }
            }
        }
    } else {
#pragma unroll
        for (int mt = 0; mt < 2; mt++) {
#pragma unroll
            for (int nt = 0; nt < 8; nt++) {
                const int col = bn + wn * 64 + nt * 8 + t * 2;
                const int row0 = bm + wm * 32 + mt * 16 + g;
                float2 v0 = make_float2(acc[mt][nt][0], acc[mt][nt][1]);
                float2 v1 = make_float2(acc[mt][nt][2], acc[mt][nt][3]);
                if (bias) {
                    float2 bb = *(const float2*)(bias + col);
                    v0.x += bb.x; v0.y += bb.y;
                    v1.x += bb.x; v1.y += bb.y;
                }
                *(float2*)(C + (long long)row0 * Dsz + col) = v0;
                *(float2*)(C + (long long)(row0 + 8) * Dsz + col) = v1;
            }
        }
    }
}

__global__ __launch_bounds__(256, 2)
void qkv_mma_kernel() {
    const unsigned short* Wh = g_wh + (long long)blockIdx.z * Dsz * Dsz;
    unsigned short* Dhi = (blockIdx.z == 0) ? g_Qh : (blockIdx.z == 1) ? g_Kh : g_Vh;
    gemm_mma(g_xh, Wh, nullptr, nullptr, Dhi);
}

__global__ __launch_bounds__(256, 2)
void out_mma_kernel(const float* __restrict__ bo, float* __restrict__ out) {
    const unsigned short* Wh = g_wh + 3ll * Dsz * Dsz;
    gemm_mma(g_ch, Wh, out, bo, nullptr);
}

// ---------------------------------------------------------------------------
// Tensor-core flash attention, causal, plain fp16. Warp owns 16 query rows.
// Round 17: diagonal-tile work skip (np > wid fully masked -> exact zeros).
// ---------------------------------------------------------------------------
#define AP 144
#define AMAT (128 * AP)
#define SM_Q 0
#define SM_KV AMAT
#define KVBUF (2 * AMAT)
#define ATT_SMEM (SM_KV + 2 * KVBUF)   // 92160 B

__global__ __launch_bounds__(256, 2)
void attn_mma_kernel() {
    extern __shared__ char smem[];
    const uint32_t sb = smem_to_u32(smem);
    const int tid = threadIdx.x;
    const int wid = tid >> 5;          // warp owns rows [wid*16, wid*16+16)
    const int lane = tid & 31;
    const int g = lane >> 2, t = lane & 3;
    const int mtx = lane >> 3, r8 = lane & 7;
    const int a_rowoff = (mtx & 1) * 8 + r8;
    const int a_segoff = (mtx >> 1);
    const int b_rowoff = (mtx >> 1) * 8 + r8;
    const int b_segoff = (mtx & 1);

    const int qb = (Ssz / 128 - 1) - blockIdx.x;
    const int q0 = qb * 128;
    const int bh = blockIdx.y;
    const int b = bh >> 4, h = bh & 15;
    const long long base = (long long)bh * Ssz * DKk;

    for (int i = tid; i < 1024; i += 256) {
        int r = i >> 3, c = i & 7;
        *(uint4*)(smem + SM_Q + r * AP + c * 16) =
            *(const uint4*)(g_Qh + base + (long long)(q0 + r) * DKk + c * 8);
    }

    auto kv_load = [&](int kt, int buf) {
        const long long rbs = base + (long long)kt * 128 * DKk;
        const unsigned short* srcs[2] = {g_Kh, g_Vh};
#pragma unroll
        for (int m = 0; m < 2; m++) {
            for (int i = tid; i < 1024; i += 256) {
                int r = i >> 3, c = i & 7;
                cp_async16(sb + SM_KV + buf * KVBUF + m * AMAT + r * AP + c * 16,
                           srcs[m] + rbs + r * DKk + c * 8);
            }
        }
        CP_COMMIT();
    };
    kv_load(0, 0);

    float oacc[8][4] = {};
    float mrow[2], lrow[2];
    mrow[0] = mrow[1] = -1e30f;
    lrow[0] = lrow[1] = 0.0f;

    const int nkt = qb + 1;
    for (int kt = 0; kt < nkt; kt++) {
        CP_WAIT0();
        __syncthreads();
        if (kt + 1 < nkt) kv_load(kt + 1, (kt + 1) & 1);

        const uint32_t kb = sb + SM_KV + (kt & 1) * KVBUF;
        const uint32_t qh_b = sb + SM_Q;
        const bool diag = (kt == qb);
        const int nplim = diag ? wid : 7;   // np > nplim fully masked -> skip

        // ---- S = Q K^T (n-pairs 0..nplim) ----
        float sacc[16][4];
#pragma unroll
        for (int ks = 0; ks < 4; ks++) {
            uint32_t ah[4];
            uint32_t ao = (uint32_t)(wid * 16 + a_rowoff) * AP +
                          (uint32_t)(ks * 2 + a_segoff) * 16;
            ldsm4(ah, qh_b + ao);
#pragma unroll
            for (int np = 0; np < 8; np++) {
                if (np > nplim) break;
                if (ks == 0) {
                    sacc[np * 2 + 0][0] = 0.f; sacc[np * 2 + 0][1] = 0.f;
                    sacc[np * 2 + 0][2] = 0.f; sacc[np * 2 + 0][3] = 0.f;
                    sacc[np * 2 + 1][0] = 0.f; sacc[np * 2 + 1][1] = 0.f;
                    sacc[np * 2 + 1][2] = 0.f; sacc[np * 2 + 1][3] = 0.f;
                }
                uint32_t bo = (uint32_t)(np * 16 + b_rowoff) * AP +
                              (uint32_t)(ks * 2 + b_segoff) * 16;
                uint32_t kh[4];
                ldsm4(kh, kb + bo);
                mma16816h(sacc[np * 2 + 0], ah, &kh[0]);
                mma16816h(sacc[np * 2 + 1], ah, &kh[2]);
            }
        }

        // ---- scale + causal mask (only np == wid needs the mask) ----
#pragma unroll
        for (int nt = 0; nt < 16; nt++) {
            if ((nt >> 1) > nplim) break;
#pragma unroll
            for (int c = 0; c < 4; c++) {
                float v = sacc[nt][c] * 0.125f;
                if (diag && (nt >> 1) == wid) {
                    int kidx = nt * 8 + t * 2 + (c & 1);
                    int qidx = wid * 16 + (c >> 1) * 8 + g;
                    if (kidx > qidx) v = -1e30f;
                }
                sacc[nt][c] = v;
            }
        }

        // ---- warp-local row max ----
        float pm[2] = {-1e30f, -1e30f};
#pragma unroll
        for (int nt = 0; nt < 16; nt++) {
            if ((nt >> 1) > nplim) break;
            pm[0] = fmaxf(pm[0], fmaxf(sacc[nt][0], sacc[nt][1]));
            pm[1] = fmaxf(pm[1], fmaxf(sacc[nt][2], sacc[nt][3]));
        }
        float alpha[2];
#pragma unroll
        for (int r = 0; r < 2; r++) {
            pm[r] = fmaxf(pm[r], __shfl_xor_sync(0xffffffffu, pm[r], 1));
            pm[r] = fmaxf(pm[r], __shfl_xor_sync(0xffffffffu, pm[r], 2));
            float mn = fmaxf(mrow[r], pm[r]);
            alpha[r] = __expf(mrow[r] - mn);
            mrow[r] = mn;
        }

        // ---- exp + row sum + immediate fp16 pack ----
        uint32_t ph[8][4];
        float psum[2] = {0.f, 0.f};
#pragma unroll
        for (int c2 = 0; c2 < 8; c2++) {
            if (c2 > nplim) break;
            float p00 = __expf(sacc[2 * c2 + 0][0] - mrow[0]);
            float p01 = __expf(sacc[2 * c2 + 0][1] - mrow[0]);
            float p02 = __expf(sacc[2 * c2 + 0][2] - mrow[1]);
            float p03 = __expf(sacc[2 * c2 + 0][3] - mrow[1]);
            float p10 = __expf(sacc[2 * c2 + 1][0] - mrow[0]);
            float p11 = __expf(sacc[2 * c2 + 1][1] - mrow[0]);
            float p12 = __expf(sacc[2 * c2 + 1][2] - mrow[1]);
            float p13 = __expf(sacc[2 * c2 + 1][3] - mrow[1]);
            psum[0] += (p00 + p01) + (p10 + p11);
            psum[1] += (p02 + p03) + (p12 + p13);
            ph[c2][0] = packh(p00, p01);
            ph[c2][1] = packh(p02, p03);
            ph[c2][2] = packh(p10, p11);
            ph[c2][3] = packh(p12, p13);
        }
#pragma unroll
        for (int r = 0; r < 2; r++) {
            psum[r] += __shfl_xor_sync(0xffffffffu, psum[r], 1);
            psum[r] += __shfl_xor_sync(0xffffffffu, psum[r], 2);
            lrow[r] = lrow[r] * alpha[r] + psum[r];
        }
#pragma unroll
        for (int nt = 0; nt < 8; nt++)
#pragma unroll
            for (int c = 0; c < 4; c++)
                oacc[nt][c] *= alpha[c >> 1];

        // ---- O += P V (key chunks 0..nplim) ----
        const uint32_t vh_b = kb + AMAT;
#pragma unroll
        for (int ks2 = 0; ks2 < 8; ks2++) {
            if (ks2 > nplim) break;
#pragma unroll
            for (int dp = 0; dp < 4; dp++) {
                uint32_t vo = (uint32_t)(ks2 * 16 + (mtx & 1) * 8 + r8) * AP +
                              (uint32_t)(dp * 16 + (mtx >> 1) * 8) * 2;
                uint32_t vh[4];
                ldsm4t(vh, vh_b + vo);
                mma16816h(oacc[dp * 2 + 0], ph[ks2], &vh[0]);
                mma16816h(oacc[dp * 2 + 1], ph[ks2], &vh[2]);
            }
        }
    }

    // ---- epilogue: normalize, write fp16 ctx ----
    float inv[2] = {1.0f / lrow[0], 1.0f / lrow[1]};
#pragma unroll
    for (int nt = 0; nt < 8; nt++)
#pragma unroll
        for (int hh = 0; hh < 2; hh++) {
            int row = wid * 16 + hh * 8 + g;
            int col = nt * 8 + t * 2;
            float v0 = oacc[nt][hh * 2 + 0] * inv[hh];
            float v1 = oacc[nt][hh * 2 + 1] * inv[hh];
            long long dst = ((long long)(b * Ssz + q0 + row)) * Dsz +
                            h * DKk + col;
            *(uint32_t*)(g_ch + dst) = packh(v0, v1);
        }
}

// ---------------------------------------------------------------------------
extern "C" void kernel_launch(void* const* d_in, const int* in_sizes, int n_in,
                              void* d_out, int out_size) {
    const float* x  = (const float*)d_in[0];
    const float* wq = (const float*)d_in[1];
    const float* wk = (const float*)d_in[2];
    const float* wv = (const float*)d_in[3];
    const float* wo = (const float*)d_in[4];
    const float* bo = (const float*)d_in[5];
    float* out = (float*)d_out;

    cudaFuncSetAttribute(qkv_mma_kernel,
                         cudaFuncAttributeMaxDynamicSharedMemorySize, GEMM_SMEM);
    cudaFuncSetAttribute(out_mma_kernel,
                         cudaFuncAttributeMaxDynamicSharedMemorySize, GEMM_SMEM);
    cudaFuncSetAttribute(attn_mma_kernel,
                         cudaFuncAttributeMaxDynamicSharedMemorySize, ATT_SMEM);

    unsigned short* xh;
    cudaGetSymbolAddress((void**)&xh, g_xh);

    const int n4x = Mrows * Dsz / 4;
    const int n4w = Dsz * Dsz / 4;

    convert_f16_kernel<<<(n4x + 255) / 256, 256>>>(
        (const float4*)x, (uint2*)xh, n4x);
    dim3 gw((n4w + 255) / 256, 4);
    convert_w_kernel<<<gw, 256>>>((const float4*)wq, (const float4*)wk,
                                  (const float4*)wv, (const float4*)wo, n4w);

    dim3 g1(Dsz / 128, Mrows / 128, 3);
    qkv_mma_kernel<<<g1, 256, GEMM_SMEM>>>();

    dim3 g2(Ssz / 128, Bsz * Hh);
    attn_mma_kernel<<<g2, 256, ATT_SMEM>>>();

    dim3 g3(Dsz / 128, Mrows / 128);
    out_mma_kernel<<<g3, 256, GEMM_SMEM>>>(bo, out);
}